// round 14
// baseline (speedup 1.0000x reference)
#include <cuda_runtime.h>
#include <cstdint>
#include <math.h>

// MMD loss: B=4096, D=256, N=2B=8192.
// loss = (1/B^2) * sum_{i,j} sign(i,j) * K(i,j),  sign = +1 same block, -1 cross.
// K(i,j) = sum_{m=0..4} exp(-L2_ij/(bw*2^m)),  bw = (sum L2)/(N^2-N)/4.
// u = exp2(L2*negc2) -> K = u+u^2+u^4+u^8+u^16.
// INT8 IMMA m16n8k32 Gram tiles (R12 skeleton: chunked double-buffer bulk-copy,
// persistent 2 CTA/SM) + anti-phase stagger of odd CTAs + prescaled epilogue
// constants. sq/bandwidth from DEQUANTIZED values (L2(i,i)==0 exactly).

#define DDIM 256
#define CHUNK_B 10240           // 128 rows x 80B (64 int8 + 16 pad), contiguous
#define TILE_B  40960           // 4 chunks
#define NCTA    296             // 2 per SM on 148-SM B200

__device__ char   g_i8[64 * TILE_B];   // quantized chunked [src; tgt]
__device__ float  g_scale[8192];       // per-row dequant scale
__device__ float  g_sq[8192];
__device__ float  g_sqn[8192];         // sq * negc2
__device__ float  g_m2sn[8192];        // -2 * scale * negc2
__device__ float  g_colsum[256];
__device__ double g_sumsq;             // sum of row sq-norms (atomic from k_prep)
__device__ float  g_negc2;
__device__ double g_accum;

// SMEM layout (dynamic): [A0 10K][A1 10K][B0 10K][B1 10K][mbar 2x8][red]
#define SM_A(buf)  ((uint32_t)(buf) * 10240u)
#define SM_B(buf)  (20480u + (uint32_t)(buf) * 10240u)
#define SM_MBAR    40960u
#define SM_RED     40992u
#define SM_TOTAL   41088

// ---------------- helpers ---------------------------------------------------
__device__ __forceinline__ uint32_t smem_u32(const void* p) {
    uint32_t a;
    asm("{ .reg .u64 t; cvta.to.shared.u64 t, %1; cvt.u32.u64 %0, t; }" : "=r"(a) : "l"(p));
    return a;
}
__device__ __forceinline__ void ldsm4(uint32_t* r, uint32_t addr) {
    asm volatile("ldmatrix.sync.aligned.m8n8.x4.shared.b16 {%0,%1,%2,%3}, [%4];"
                 : "=r"(r[0]), "=r"(r[1]), "=r"(r[2]), "=r"(r[3]) : "r"(addr));
}
__device__ __forceinline__ void mma16832s8(int* c, const uint32_t* a, const uint32_t* b) {
    asm volatile(
        "mma.sync.aligned.m16n8k32.row.col.s32.s8.s8.s32 "
        "{%0,%1,%2,%3}, {%4,%5,%6,%7}, {%8,%9}, {%0,%1,%2,%3};"
        : "+r"(c[0]), "+r"(c[1]), "+r"(c[2]), "+r"(c[3])
        : "r"(a[0]), "r"(a[1]), "r"(a[2]), "r"(a[3]), "r"(b[0]), "r"(b[1]));
}
__device__ __forceinline__ void bulk_g2s(uint32_t dst, const void* src,
                                         uint32_t bytes, uint32_t mbar) {
    asm volatile(
        "cp.async.bulk.shared::cluster.global.mbarrier::complete_tx::bytes [%0], [%1], %2, [%3];"
        :: "r"(dst), "l"(src), "r"(bytes), "r"(mbar) : "memory");
}
#define MB_INIT(mb, c) asm volatile("mbarrier.init.shared.b64 [%0], %1;" :: "r"(mb), "r"(c) : "memory")
#define MB_EXPECT_TX(mb, n) asm volatile("mbarrier.arrive.expect_tx.shared.b64 _, [%0], %1;" :: "r"(mb), "r"(n) : "memory")
#define MB_WAIT(mb, par) do {                                                 \
    uint32_t _m = (mb), _p = (par), _d;                                       \
    asm volatile("{\n\t.reg .pred p;\n\t"                                     \
        "mbarrier.try_wait.parity.acquire.cta.shared::cta.b64 p, [%1], %2;\n\t" \
        "selp.b32 %0, 1, 0, p;\n\t}" : "=r"(_d) : "r"(_m), "r"(_p) : "memory"); \
    if (!_d) {                                                                \
        asm volatile("{\n\t.reg .pred P1;\n\t"                                \
            "W_%=:\n\t"                                                       \
            "mbarrier.try_wait.parity.acquire.cta.shared::cta.b64 P1, [%0], %1, 0x989680;\n\t" \
            "@P1 bra.uni D_%=;\n\t"                                           \
            "bra.uni W_%=;\n\t"                                               \
            "D_%=:\n\t}" :: "r"(_m), "r"(_p) : "memory");                     \
    }                                                                         \
} while (0)

__device__ __forceinline__ float fast_ex2(float x) {
    float r;
    asm("ex2.approx.ftz.f32 %0, %1;" : "=f"(r) : "f"(x));
    return r;
}
typedef unsigned long long u64t;
__device__ __forceinline__ u64t f2pack(float lo, float hi) {
    u64t r; asm("mov.b64 %0, {%1, %2};" : "=l"(r) : "f"(lo), "f"(hi)); return r;
}
__device__ __forceinline__ void f2unpack(u64t v, float& lo, float& hi) {
    asm("mov.b64 {%0, %1}, %2;" : "=f"(lo), "=f"(hi) : "l"(v));
}
__device__ __forceinline__ u64t f2fma(u64t a, u64t b, u64t c) {
    u64t d; asm("fma.rn.f32x2 %0, %1, %2, %3;" : "=l"(d) : "l"(a), "l"(b), "l"(c)); return d;
}
__device__ __forceinline__ void tri_decode(int idx, int NT, int& ti, int& tj) {
    float fn = (float)NT + 0.5f;
    int a = (int)(fn - sqrtf(fn * fn - 2.0f * (float)idx));
    while (a * NT - (a * (a - 1)) / 2 > idx) --a;
    while ((a + 1) * NT - ((a + 1) * a) / 2 <= idx) ++a;
    ti = a;
    tj = a + (idx - (a * NT - (a * (a - 1)) / 2));
}

// ---------------------------------------------------------------------------
__global__ void k_zero() {
    g_colsum[threadIdx.x] = 0.f;
    if (threadIdx.x == 0) { g_accum = 0.0; g_sumsq = 0.0; }
}

// ---------------------------------------------------------------------------
// Quantize rows to int8 (per-row symmetric scale) into the padded chunked
// layout; row sq-norms / colsums / total sumsq FROM THE DEQUANTIZED values.
__global__ void k_prep(const float* __restrict__ src,
                       const float* __restrict__ tgt, int B) {
    __shared__ float scol[256];
    __shared__ float swsum[8];
    scol[threadIdx.x] = 0.f;
    __syncthreads();

    const int warp = threadIdx.x >> 5;
    const int lane = threadIdx.x & 31;
    const int rowBase = blockIdx.x * 64 + warp * 8;

    float c0 = 0.f, c1 = 0.f, c2 = 0.f, c3 = 0.f;
    float c4 = 0.f, c5 = 0.f, c6 = 0.f, c7 = 0.f;
    float wss = 0.f;   // per-warp total of row sq-norms

    const int ca = lane * 4;
    const int cb = 128 + lane * 4;

    #pragma unroll
    for (int r = 0; r < 8; ++r) {
        const int row = rowBase + r;
        const float* rp = (row < B) ? (src + (size_t)row * DDIM)
                                    : (tgt + (size_t)(row - B) * DDIM);
        float4 v0 = *(const float4*)(rp + ca);
        float4 v1 = *(const float4*)(rp + cb);

        float am = fmaxf(fmaxf(fmaxf(fabsf(v0.x), fabsf(v0.y)),
                               fmaxf(fabsf(v0.z), fabsf(v0.w))),
                         fmaxf(fmaxf(fabsf(v1.x), fabsf(v1.y)),
                               fmaxf(fabsf(v1.z), fabsf(v1.w))));
        #pragma unroll
        for (int o = 16; o; o >>= 1)
            am = fmaxf(am, __shfl_xor_sync(0xffffffffu, am, o));

        const float s   = am * (1.0f / 127.0f);
        const float inv = (am > 0.f) ? 127.0f / am : 0.f;

        int q0 = __float2int_rn(v0.x * inv), q1 = __float2int_rn(v0.y * inv);
        int q2 = __float2int_rn(v0.z * inv), q3 = __float2int_rn(v0.w * inv);
        int q4 = __float2int_rn(v1.x * inv), q5 = __float2int_rn(v1.y * inv);
        int q6 = __float2int_rn(v1.z * inv), q7 = __float2int_rn(v1.w * inv);

        uint32_t pk0 = (uint32_t)(q0 & 0xff) | ((uint32_t)(q1 & 0xff) << 8)
                     | ((uint32_t)(q2 & 0xff) << 16) | ((uint32_t)(q3 & 0xff) << 24);
        uint32_t pk1 = (uint32_t)(q4 & 0xff) | ((uint32_t)(q5 & 0xff) << 8)
                     | ((uint32_t)(q6 & 0xff) << 16) | ((uint32_t)(q7 & 0xff) << 24);

        const int tile = row >> 7, rl = row & 127;
        size_t base = (size_t)tile * TILE_B + (size_t)rl * 80;
        *(uint32_t*)(g_i8 + base + (size_t)(ca >> 6) * CHUNK_B + (ca & 63)) = pk0;
        *(uint32_t*)(g_i8 + base + (size_t)(cb >> 6) * CHUNK_B + (cb & 63)) = pk1;

        float d0 = (float)q0 * s, d1 = (float)q1 * s, d2 = (float)q2 * s, d3 = (float)q3 * s;
        float d4 = (float)q4 * s, d5 = (float)q5 * s, d6 = (float)q6 * s, d7 = (float)q7 * s;

        float ss = d0*d0 + d1*d1 + d2*d2 + d3*d3 + d4*d4 + d5*d5 + d6*d6 + d7*d7;
        #pragma unroll
        for (int o = 16; o; o >>= 1) ss += __shfl_xor_sync(0xffffffffu, ss, o);
        if (lane == 0) { g_sq[row] = ss; g_scale[row] = s; wss += ss; }

        c0 += d0; c1 += d1; c2 += d2; c3 += d3;
        c4 += d4; c5 += d5; c6 += d6; c7 += d7;
    }

    atomicAdd(&scol[lane * 4 + 0], c0);
    atomicAdd(&scol[lane * 4 + 1], c1);
    atomicAdd(&scol[lane * 4 + 2], c2);
    atomicAdd(&scol[lane * 4 + 3], c3);
    atomicAdd(&scol[128 + lane * 4 + 0], c4);
    atomicAdd(&scol[128 + lane * 4 + 1], c5);
    atomicAdd(&scol[128 + lane * 4 + 2], c6);
    atomicAdd(&scol[128 + lane * 4 + 3], c7);
    if (lane == 0) swsum[warp] = wss;
    __syncthreads();
    atomicAdd(&g_colsum[threadIdx.x], scol[threadIdx.x]);
    if (threadIdx.x == 0) {
        float bs = 0.f;
        #pragma unroll
        for (int w = 0; w < 8; ++w) bs += swsum[w];
        atomicAdd(&g_sumsq, (double)bs);
    }
}

// ---------------------------------------------------------------------------
// Bandwidth + prescale of epilogue constants (single block, one launch).
__global__ void k_bw(int B) {
    const int N = 2 * B;
    __shared__ double sh[256];
    __shared__ float sh_nc;
    const int t = threadIdx.x;

    float c = g_colsum[t];
    sh[t] = (double)c * (double)c;
    __syncthreads();
    for (int st = 128; st; st >>= 1) {
        if (t < st) sh[t] += sh[t + st];
        __syncthreads();
    }
    if (t == 0) {
        double ssq   = sh[0];
        double sumL2 = 2.0 * (double)N * g_sumsq - 2.0 * ssq;
        double bw    = sumL2 / ((double)N * (double)N - (double)N);
        bw /= 4.0;  // KERNEL_MUL^(KERNEL_NUM//2) = 2^2
        float nc = (float)(-1.4426950408889634 / (16.0 * bw));
        g_negc2 = nc;
        sh_nc   = nc;
        g_accum = 0.0;
    }
    __syncthreads();
    const float nc = sh_nc;
    for (int i = t; i < N; i += 256) {
        g_sqn[i]  = g_sq[i] * nc;
        g_m2sn[i] = -2.f * g_scale[i] * nc;
    }
}

// ---------------------------------------------------------------------------
// Persistent: each CTA loops over upper-triangular 128x128 tiles.
// 8 warps (4x2), 32x64 per warp, s32 accumulators. K in 4 chunks of 64
// (2 x k32 mma steps each), double-buffered via cp.async.bulk; NEXT tile's
// chunks prefetched under the epilogue. Odd CTAs stagger ~3000 cyc so the
// two co-resident CTAs run anti-phased (mainloop overlaps partner epilogue).
__global__ void __launch_bounds__(256, 2) k_mmd(int B, int NT, int ntri) {
    extern __shared__ __align__(16) char smem[];
    const uint32_t sbase = smem_u32(smem);
    const int t = threadIdx.x;
    const int wid = t >> 5, lane = t & 31;

    if (t == 0) {
        MB_INIT(sbase + SM_MBAR, 1);
        MB_INIT(sbase + SM_MBAR + 8, 1);
    }
    __syncthreads();

    // anti-phase stagger: odd CTAs delay ~half a tile
    if (blockIdx.x & 1) {
        unsigned long long s0 = clock64();
        while (clock64() - s0 < 3000ull) { }
    }

    // warp tile: rows (wid&3)*32, cols (wid>>2)*64
    const int wrow = (wid & 3) * 32;
    const int wcol = (wid >> 2) * 64;
    const uint32_t aThr = (uint32_t)(((lane >> 3) & 1) * 8 + (lane & 7)) * 80
                        + (uint32_t)(lane >> 4) * 16;
    const uint32_t bThr = (uint32_t)((lane >> 4) * 8 + (lane & 7)) * 80
                        + (uint32_t)((lane >> 3) & 1) * 16;
    uint32_t aRowOff[2], bRowOff[4];
    #pragma unroll
    for (int m = 0; m < 2; ++m)
        aRowOff[m] = (uint32_t)(wrow + m * 16) * 80 + aThr;
    #pragma unroll
    for (int p = 0; p < 4; ++p)
        bRowOff[p] = (uint32_t)(wcol + p * 16) * 80 + bThr;

    int idx = blockIdx.x;
    if (idx >= ntri) return;
    int ti, tj;
    tri_decode(idx, NT, ti, tj);

    int ph0 = 0, ph1 = 0;

    if (t == 0) {
        const char* gA = g_i8 + (size_t)ti * TILE_B;
        const char* gB = g_i8 + (size_t)tj * TILE_B;
        MB_EXPECT_TX(sbase + SM_MBAR, 2 * CHUNK_B);
        bulk_g2s(sbase + SM_A(0), gA, CHUNK_B, sbase + SM_MBAR);
        bulk_g2s(sbase + SM_B(0), gB, CHUNK_B, sbase + SM_MBAR);
        MB_EXPECT_TX(sbase + SM_MBAR + 8, 2 * CHUNK_B);
        bulk_g2s(sbase + SM_A(1), gA + CHUNK_B, CHUNK_B, sbase + SM_MBAR + 8);
        bulk_g2s(sbase + SM_B(1), gB + CHUNK_B, CHUNK_B, sbase + SM_MBAR + 8);
    }

    const u64t ZERO = 0ull;
    const u64t ONE  = f2pack(1.f, 1.f);

    while (true) {
        const int nidx = idx + gridDim.x;
        const bool has_next = (nidx < ntri);
        int ti2 = 0, tj2 = 0;
        if (has_next) tri_decode(nidx, NT, ti2, tj2);
        const char* gA2 = g_i8 + (size_t)ti2 * TILE_B;
        const char* gB2 = g_i8 + (size_t)tj2 * TILE_B;

        int acc[2][8][4];
        #pragma unroll
        for (int m = 0; m < 2; ++m)
            #pragma unroll
            for (int n = 0; n < 8; ++n)
                #pragma unroll
                for (int r = 0; r < 4; ++r) acc[m][n][r] = 0;

        #pragma unroll 1
        for (int c = 0; c < 4; ++c) {
            const int buf = c & 1;
            if (buf == 0) { MB_WAIT(sbase + SM_MBAR,     ph0 & 1); ++ph0; }
            else          { MB_WAIT(sbase + SM_MBAR + 8, ph1 & 1); ++ph1; }

            const uint32_t aB = sbase + SM_A(buf);
            const uint32_t bB = sbase + SM_B(buf);
            #pragma unroll
            for (int ks = 0; ks < 2; ++ks) {
                const uint32_t koff = (uint32_t)(ks * 32);
                uint32_t af[2][4], bf_[4][4];
                #pragma unroll
                for (int m = 0; m < 2; ++m)
                    ldsm4(af[m], aB + aRowOff[m] + koff);
                #pragma unroll
                for (int p = 0; p < 4; ++p)
                    ldsm4(bf_[p], bB + bRowOff[p] + koff);

                #pragma unroll
                for (int m = 0; m < 2; ++m)
                    #pragma unroll
                    for (int p = 0; p < 4; ++p) {
                        mma16832s8(acc[m][2 * p],     af[m], &bf_[p][0]);
                        mma16832s8(acc[m][2 * p + 1], af[m], &bf_[p][2]);
                    }
            }
            __syncthreads();
            if (t == 0) {
                if (c < 2) {
                    const char* gA1 = g_i8 + (size_t)ti * TILE_B;
                    const char* gB1 = g_i8 + (size_t)tj * TILE_B;
                    const uint32_t mb = sbase + SM_MBAR + (uint32_t)buf * 8;
                    MB_EXPECT_TX(mb, 2 * CHUNK_B);
                    bulk_g2s(sbase + SM_A(buf), gA1 + (size_t)(c + 2) * CHUNK_B, CHUNK_B, mb);
                    bulk_g2s(sbase + SM_B(buf), gB1 + (size_t)(c + 2) * CHUNK_B, CHUNK_B, mb);
                } else if (has_next) {
                    const uint32_t mb = sbase + SM_MBAR + (uint32_t)buf * 8;
                    MB_EXPECT_TX(mb, 2 * CHUNK_B);
                    bulk_g2s(sbase + SM_A(buf), gA2 + (size_t)(c - 2) * CHUNK_B, CHUNK_B, mb);
                    bulk_g2s(sbase + SM_B(buf), gB2 + (size_t)(c - 2) * CHUNK_B, CHUNK_B, mb);
                }
            }
        }

        // -------- fused epilogue (packed f32x2, prescaled constants) --------
        // C[row][col]: row = wrow + m*16 + (lane>>2) + 8*h
        //              col = wcol + n*8 + (lane&3)*2 + {0,1}
        const int   rA = wrow + (lane >> 2);
        const int   cB = wcol + (lane & 3) * 2;
        const float* sqanRow = g_sqn   + ti * 128 + rA;
        const float* scaRow  = g_scale + ti * 128 + rA;
        const float* sqbnRow = g_sqn   + tj * 128 + cB;
        const float* m2snRow = g_m2sn  + tj * 128 + cB;

        u64t sanDup[4], siDup[4];
        #pragma unroll
        for (int m = 0; m < 2; ++m)
            #pragma unroll
            for (int h = 0; h < 2; ++h) {
                float va = sqanRow[m * 16 + h * 8];
                float vs = scaRow[m * 16 + h * 8];
                sanDup[m * 2 + h] = f2pack(va, va);
                siDup[m * 2 + h]  = f2pack(vs, vs);
            }
        u64t sbn[8], m2snj[8];
        #pragma unroll
        for (int n = 0; n < 8; ++n) {
            sbn[n]   = *(const u64t*)(sqbnRow + n * 8);
            m2snj[n] = *(const u64t*)(m2snRow + n * 8);
        }

        u64t tsp = ZERO;
        #pragma unroll
        for (int m = 0; m < 2; ++m)
            #pragma unroll
            for (int n = 0; n < 8; ++n)
                #pragma unroll
                for (int h = 0; h < 2; ++h) {
                    float f0 = __int2float_rn(acc[m][n][2 * h]);
                    float f1 = __int2float_rn(acc[m][n][2 * h + 1]);
                    u64t dp   = f2pack(f0, f1);
                    u64t tpd  = f2fma(dp, siDup[m * 2 + h], ZERO);      // acc*s_i
                    u64t sums = f2fma(sanDup[m * 2 + h], ONE, sbn[n]);  // (sqa+sqb)*nc
                    u64t xp   = f2fma(tpd, m2snj[n], sums);             // L2*negc2
                    float x0, x1;
                    f2unpack(xp, x0, x1);
                    u64t up  = f2pack(fast_ex2(x0), fast_ex2(x1));
                    u64t a_  = f2fma(up, up, up);        // u^2 + u
                    u64t u2  = f2fma(up, up, ZERO);
                    u64t u4  = f2fma(u2, u2, ZERO);
                    u64t b_  = f2fma(u4, u4, u4);        // u^8 + u^4
                    u64t u8  = f2fma(u4, u4, ZERO);
                    tsp = f2fma(u8, u8, tsp);            // + u^16
                    tsp = f2fma(a_, ONE, tsp);
                    tsp = f2fma(b_, ONE, tsp);
                }
        float tlo, thi;
        f2unpack(tsp, tlo, thi);
        float tsum = tlo + thi;

        #pragma unroll
        for (int o = 16; o; o >>= 1) tsum += __shfl_xor_sync(0xffffffffu, tsum, o);
        float* red = (float*)(smem + SM_RED);
        if (lane == 0) red[wid] = tsum;
        __syncthreads();
        if (wid == 0) {
            float v = (lane < 8) ? red[lane] : 0.f;
            #pragma unroll
            for (int o = 4; o; o >>= 1) v += __shfl_xor_sync(0xffffffffu, v, o);
            if (lane == 0) {
                bool  si   = (ti * 128) < B;
                bool  sj   = (tj * 128) < B;
                float w    = (ti == tj) ? 1.f : 2.f;
                float sgnw = (si == sj) ? w : -w;
                atomicAdd(&g_accum, (double)(v * sgnw));
            }
        }

        if (!has_next) break;
        idx = nidx; ti = ti2; tj = tj2;
    }
}

// ---------------------------------------------------------------------------
__global__ void k_final(float* out, int B) {
    out[0] = (float)(g_accum / ((double)B * (double)B));
}

// ---------------------------------------------------------------------------
extern "C" void kernel_launch(void* const* d_in, const int* in_sizes, int n_in,
                              void* d_out, int out_size) {
    const float* src = (const float*)d_in[0];
    const float* tgt = (const float*)d_in[1];
    const int B = in_sizes[0] / DDIM;   // 4096
    const int N = 2 * B;                // 8192
    const int NT = N / 128;             // 64

    cudaFuncSetAttribute(k_mmd, cudaFuncAttributeMaxDynamicSharedMemorySize, SM_TOTAL);

    k_zero<<<1, 256>>>();
    k_prep<<<N / 64, 256>>>(src, tgt, B);
    k_bw<<<1, 256>>>(B);
    const int ntri = NT * (NT + 1) / 2; // 2080
    const int ncta = (ntri < NCTA) ? ntri : NCTA;
    k_mmd<<<ncta, 256, SM_TOTAL>>>(B, NT, ntri);
    k_final<<<1, 1>>>((float*)d_out, B);
}

// round 15
// speedup vs baseline: 1.3381x; 1.3381x over previous
#include <cuda_runtime.h>
#include <cstdint>
#include <math.h>

// MMD loss: B=4096, D=256, N=2B=8192.
// loss = (1/B^2) * sum_{i,j} sign(i,j) * K(i,j),  sign = +1 same block, -1 cross.
// K(i,j) = sum_{m=0..4} exp(-L2_ij/(bw*2^m)),  bw = (sum L2)/(N^2-N)/4.
// u = exp2(L2*negc2) -> K = u+u^2+u^4+u^8+u^16.
// INT8 IMMA m16n8k32 Gram tiles (R12 skeleton: chunked double-buffer bulk-copy,
// persistent 2 CTA/SM, anti-phase stagger). sq/bandwidth from DEQUANTIZED
// values (L2(i,i)==0 exactly). 4 launches only; k_bw self-cleans state so
// every graph replay starts from zeroed accumulators.

#define DDIM 256
#define CHUNK_B 10240           // 128 rows x 80B (64 int8 + 16 pad), contiguous
#define TILE_B  40960           // 4 chunks
#define NCTA    296             // 2 per SM on 148-SM B200

__device__ char   g_i8[64 * TILE_B];   // quantized chunked [src; tgt]
__device__ float  g_scale[8192];       // per-row dequant scale
__device__ float  g_sq[8192];
__device__ float  g_colsum[256];       // zero-init; re-zeroed by k_bw each run
__device__ double g_sumsq;             // zero-init; re-zeroed by k_bw each run
__device__ float  g_negc2;
__device__ double g_accum;             // reset by k_bw each run

// SMEM layout (dynamic): [A0 10K][A1 10K][B0 10K][B1 10K][mbar 2x8][red]
#define SM_A(buf)  ((uint32_t)(buf) * 10240u)
#define SM_B(buf)  (20480u + (uint32_t)(buf) * 10240u)
#define SM_MBAR    40960u
#define SM_RED     40992u
#define SM_TOTAL   41088

// ---------------- helpers ---------------------------------------------------
__device__ __forceinline__ uint32_t smem_u32(const void* p) {
    uint32_t a;
    asm("{ .reg .u64 t; cvta.to.shared.u64 t, %1; cvt.u32.u64 %0, t; }" : "=r"(a) : "l"(p));
    return a;
}
__device__ __forceinline__ void ldsm4(uint32_t* r, uint32_t addr) {
    asm volatile("ldmatrix.sync.aligned.m8n8.x4.shared.b16 {%0,%1,%2,%3}, [%4];"
                 : "=r"(r[0]), "=r"(r[1]), "=r"(r[2]), "=r"(r[3]) : "r"(addr));
}
__device__ __forceinline__ void mma16832s8(int* c, const uint32_t* a, const uint32_t* b) {
    asm volatile(
        "mma.sync.aligned.m16n8k32.row.col.s32.s8.s8.s32 "
        "{%0,%1,%2,%3}, {%4,%5,%6,%7}, {%8,%9}, {%0,%1,%2,%3};"
        : "+r"(c[0]), "+r"(c[1]), "+r"(c[2]), "+r"(c[3])
        : "r"(a[0]), "r"(a[1]), "r"(a[2]), "r"(a[3]), "r"(b[0]), "r"(b[1]));
}
__device__ __forceinline__ void bulk_g2s(uint32_t dst, const void* src,
                                         uint32_t bytes, uint32_t mbar) {
    asm volatile(
        "cp.async.bulk.shared::cluster.global.mbarrier::complete_tx::bytes [%0], [%1], %2, [%3];"
        :: "r"(dst), "l"(src), "r"(bytes), "r"(mbar) : "memory");
}
#define MB_INIT(mb, c) asm volatile("mbarrier.init.shared.b64 [%0], %1;" :: "r"(mb), "r"(c) : "memory")
#define MB_EXPECT_TX(mb, n) asm volatile("mbarrier.arrive.expect_tx.shared.b64 _, [%0], %1;" :: "r"(mb), "r"(n) : "memory")
#define MB_WAIT(mb, par) do {                                                 \
    uint32_t _m = (mb), _p = (par), _d;                                       \
    asm volatile("{\n\t.reg .pred p;\n\t"                                     \
        "mbarrier.try_wait.parity.acquire.cta.shared::cta.b64 p, [%1], %2;\n\t" \
        "selp.b32 %0, 1, 0, p;\n\t}" : "=r"(_d) : "r"(_m), "r"(_p) : "memory"); \
    if (!_d) {                                                                \
        asm volatile("{\n\t.reg .pred P1;\n\t"                                \
            "W_%=:\n\t"                                                       \
            "mbarrier.try_wait.parity.acquire.cta.shared::cta.b64 P1, [%0], %1, 0x989680;\n\t" \
            "@P1 bra.uni D_%=;\n\t"                                           \
            "bra.uni W_%=;\n\t"                                               \
            "D_%=:\n\t}" :: "r"(_m), "r"(_p) : "memory");                     \
    }                                                                         \
} while (0)

__device__ __forceinline__ float fast_ex2(float x) {
    float r;
    asm("ex2.approx.ftz.f32 %0, %1;" : "=f"(r) : "f"(x));
    return r;
}
typedef unsigned long long u64t;
__device__ __forceinline__ u64t f2pack(float lo, float hi) {
    u64t r; asm("mov.b64 %0, {%1, %2};" : "=l"(r) : "f"(lo), "f"(hi)); return r;
}
__device__ __forceinline__ void f2unpack(u64t v, float& lo, float& hi) {
    asm("mov.b64 {%0, %1}, %2;" : "=f"(lo), "=f"(hi) : "l"(v));
}
__device__ __forceinline__ u64t f2fma(u64t a, u64t b, u64t c) {
    u64t d; asm("fma.rn.f32x2 %0, %1, %2, %3;" : "=l"(d) : "l"(a), "l"(b), "l"(c)); return d;
}
__device__ __forceinline__ void tri_decode(int idx, int NT, int& ti, int& tj) {
    float fn = (float)NT + 0.5f;
    int a = (int)(fn - sqrtf(fn * fn - 2.0f * (float)idx));
    while (a * NT - (a * (a - 1)) / 2 > idx) --a;
    while ((a + 1) * NT - ((a + 1) * a) / 2 <= idx) ++a;
    ti = a;
    tj = a + (idx - (a * NT - (a * (a - 1)) / 2));
}

// ---------------------------------------------------------------------------
// Quantize rows to int8 (per-row symmetric scale) into the padded chunked
// layout; row sq-norms / colsums / total sumsq FROM THE DEQUANTIZED values.
// Requires g_colsum/g_sumsq zeroed on entry (static init or k_bw cleanup).
__global__ void k_prep(const float* __restrict__ src,
                       const float* __restrict__ tgt, int B) {
    __shared__ float scol[256];
    __shared__ float swsum[8];
    scol[threadIdx.x] = 0.f;
    __syncthreads();

    const int warp = threadIdx.x >> 5;
    const int lane = threadIdx.x & 31;
    const int rowBase = blockIdx.x * 64 + warp * 8;

    float c0 = 0.f, c1 = 0.f, c2 = 0.f, c3 = 0.f;
    float c4 = 0.f, c5 = 0.f, c6 = 0.f, c7 = 0.f;
    float wss = 0.f;

    const int ca = lane * 4;
    const int cb = 128 + lane * 4;

    #pragma unroll
    for (int r = 0; r < 8; ++r) {
        const int row = rowBase + r;
        const float* rp = (row < B) ? (src + (size_t)row * DDIM)
                                    : (tgt + (size_t)(row - B) * DDIM);
        float4 v0 = *(const float4*)(rp + ca);
        float4 v1 = *(const float4*)(rp + cb);

        float am = fmaxf(fmaxf(fmaxf(fabsf(v0.x), fabsf(v0.y)),
                               fmaxf(fabsf(v0.z), fabsf(v0.w))),
                         fmaxf(fmaxf(fabsf(v1.x), fabsf(v1.y)),
                               fmaxf(fabsf(v1.z), fabsf(v1.w))));
        #pragma unroll
        for (int o = 16; o; o >>= 1)
            am = fmaxf(am, __shfl_xor_sync(0xffffffffu, am, o));

        const float s   = am * (1.0f / 127.0f);
        const float inv = (am > 0.f) ? 127.0f / am : 0.f;

        int q0 = __float2int_rn(v0.x * inv), q1 = __float2int_rn(v0.y * inv);
        int q2 = __float2int_rn(v0.z * inv), q3 = __float2int_rn(v0.w * inv);
        int q4 = __float2int_rn(v1.x * inv), q5 = __float2int_rn(v1.y * inv);
        int q6 = __float2int_rn(v1.z * inv), q7 = __float2int_rn(v1.w * inv);

        uint32_t pk0 = (uint32_t)(q0 & 0xff) | ((uint32_t)(q1 & 0xff) << 8)
                     | ((uint32_t)(q2 & 0xff) << 16) | ((uint32_t)(q3 & 0xff) << 24);
        uint32_t pk1 = (uint32_t)(q4 & 0xff) | ((uint32_t)(q5 & 0xff) << 8)
                     | ((uint32_t)(q6 & 0xff) << 16) | ((uint32_t)(q7 & 0xff) << 24);

        const int tile = row >> 7, rl = row & 127;
        size_t base = (size_t)tile * TILE_B + (size_t)rl * 80;
        *(uint32_t*)(g_i8 + base + (size_t)(ca >> 6) * CHUNK_B + (ca & 63)) = pk0;
        *(uint32_t*)(g_i8 + base + (size_t)(cb >> 6) * CHUNK_B + (cb & 63)) = pk1;

        float d0 = (float)q0 * s, d1 = (float)q1 * s, d2 = (float)q2 * s, d3 = (float)q3 * s;
        float d4 = (float)q4 * s, d5 = (float)q5 * s, d6 = (float)q6 * s, d7 = (float)q7 * s;

        float ss = d0*d0 + d1*d1 + d2*d2 + d3*d3 + d4*d4 + d5*d5 + d6*d6 + d7*d7;
        #pragma unroll
        for (int o = 16; o; o >>= 1) ss += __shfl_xor_sync(0xffffffffu, ss, o);
        if (lane == 0) { g_sq[row] = ss; g_scale[row] = s; wss += ss; }

        c0 += d0; c1 += d1; c2 += d2; c3 += d3;
        c4 += d4; c5 += d5; c6 += d6; c7 += d7;
    }

    atomicAdd(&scol[lane * 4 + 0], c0);
    atomicAdd(&scol[lane * 4 + 1], c1);
    atomicAdd(&scol[lane * 4 + 2], c2);
    atomicAdd(&scol[lane * 4 + 3], c3);
    atomicAdd(&scol[128 + lane * 4 + 0], c4);
    atomicAdd(&scol[128 + lane * 4 + 1], c5);
    atomicAdd(&scol[128 + lane * 4 + 2], c6);
    atomicAdd(&scol[128 + lane * 4 + 3], c7);
    if (lane == 0) swsum[warp] = wss;
    __syncthreads();
    atomicAdd(&g_colsum[threadIdx.x], scol[threadIdx.x]);
    if (threadIdx.x == 0) {
        float bs = 0.f;
        #pragma unroll
        for (int w = 0; w < 8; ++w) bs += swsum[w];
        atomicAdd(&g_sumsq, (double)bs);
    }
}

// ---------------------------------------------------------------------------
// Bandwidth (single block, minimal work). Consumes and RE-ZEROES g_colsum and
// g_sumsq so the next graph replay starts clean; resets g_accum.
__global__ void k_bw(int B) {
    const int N = 2 * B;
    __shared__ double sh[256];
    const int t = threadIdx.x;

    float c = g_colsum[t];
    sh[t] = (double)c * (double)c;
    __syncthreads();
    for (int st = 128; st; st >>= 1) {
        if (t < st) sh[t] += sh[t + st];
        __syncthreads();
    }
    g_colsum[t] = 0.f;          // cleanup for next replay
    if (t == 0) {
        double ssq   = sh[0];
        double sumL2 = 2.0 * (double)N * g_sumsq - 2.0 * ssq;
        double bw    = sumL2 / ((double)N * (double)N - (double)N);
        bw /= 4.0;  // KERNEL_MUL^(KERNEL_NUM//2) = 2^2
        g_negc2 = (float)(-1.4426950408889634 / (16.0 * bw));
        g_sumsq = 0.0;          // cleanup for next replay
        g_accum = 0.0;
    }
}

// ---------------------------------------------------------------------------
// Persistent: each CTA loops over upper-triangular 128x128 tiles.
// 8 warps (4x2), 32x64 per warp, s32 accumulators. K in 4 chunks of 64
// (2 x k32 mma steps each), double-buffered via cp.async.bulk; NEXT tile's
// chunks prefetched under the epilogue. Odd CTAs stagger ~3000 cyc so the
// co-resident CTAs run anti-phased.
__global__ void __launch_bounds__(256, 2) k_mmd(int B, int NT, int ntri) {
    extern __shared__ __align__(16) char smem[];
    const uint32_t sbase = smem_u32(smem);
    const int t = threadIdx.x;
    const int wid = t >> 5, lane = t & 31;

    if (t == 0) {
        MB_INIT(sbase + SM_MBAR, 1);
        MB_INIT(sbase + SM_MBAR + 8, 1);
    }
    __syncthreads();

    // anti-phase stagger: odd CTAs delay ~half a tile
    if (blockIdx.x & 1) {
        unsigned long long s0 = clock64();
        while (clock64() - s0 < 3000ull) { }
    }

    const int wrow = (wid & 3) * 32;
    const int wcol = (wid >> 2) * 64;
    const uint32_t aThr = (uint32_t)(((lane >> 3) & 1) * 8 + (lane & 7)) * 80
                        + (uint32_t)(lane >> 4) * 16;
    const uint32_t bThr = (uint32_t)((lane >> 4) * 8 + (lane & 7)) * 80
                        + (uint32_t)((lane >> 3) & 1) * 16;
    uint32_t aRowOff[2], bRowOff[4];
    #pragma unroll
    for (int m = 0; m < 2; ++m)
        aRowOff[m] = (uint32_t)(wrow + m * 16) * 80 + aThr;
    #pragma unroll
    for (int p = 0; p < 4; ++p)
        bRowOff[p] = (uint32_t)(wcol + p * 16) * 80 + bThr;

    int idx = blockIdx.x;
    if (idx >= ntri) return;
    int ti, tj;
    tri_decode(idx, NT, ti, tj);

    int ph0 = 0, ph1 = 0;

    if (t == 0) {
        const char* gA = g_i8 + (size_t)ti * TILE_B;
        const char* gB = g_i8 + (size_t)tj * TILE_B;
        MB_EXPECT_TX(sbase + SM_MBAR, 2 * CHUNK_B);
        bulk_g2s(sbase + SM_A(0), gA, CHUNK_B, sbase + SM_MBAR);
        bulk_g2s(sbase + SM_B(0), gB, CHUNK_B, sbase + SM_MBAR);
        MB_EXPECT_TX(sbase + SM_MBAR + 8, 2 * CHUNK_B);
        bulk_g2s(sbase + SM_A(1), gA + CHUNK_B, CHUNK_B, sbase + SM_MBAR + 8);
        bulk_g2s(sbase + SM_B(1), gB + CHUNK_B, CHUNK_B, sbase + SM_MBAR + 8);
    }

    const float negc2 = g_negc2;
    const u64t ZERO = 0ull;
    const u64t ONE  = f2pack(1.f, 1.f);
    const u64t M2   = f2pack(-2.f, -2.f);
    const u64t NCD  = f2pack(negc2, negc2);

    while (true) {
        const int nidx = idx + gridDim.x;
        const bool has_next = (nidx < ntri);
        int ti2 = 0, tj2 = 0;
        if (has_next) tri_decode(nidx, NT, ti2, tj2);
        const char* gA2 = g_i8 + (size_t)ti2 * TILE_B;
        const char* gB2 = g_i8 + (size_t)tj2 * TILE_B;

        int acc[2][8][4];
        #pragma unroll
        for (int m = 0; m < 2; ++m)
            #pragma unroll
            for (int n = 0; n < 8; ++n)
                #pragma unroll
                for (int r = 0; r < 4; ++r) acc[m][n][r] = 0;

        #pragma unroll 1
        for (int c = 0; c < 4; ++c) {
            const int buf = c & 1;
            if (buf == 0) { MB_WAIT(sbase + SM_MBAR,     ph0 & 1); ++ph0; }
            else          { MB_WAIT(sbase + SM_MBAR + 8, ph1 & 1); ++ph1; }

            const uint32_t aB = sbase + SM_A(buf);
            const uint32_t bB = sbase + SM_B(buf);
            #pragma unroll
            for (int ks = 0; ks < 2; ++ks) {
                const uint32_t koff = (uint32_t)(ks * 32);
                uint32_t af[2][4], bf_[4][4];
                #pragma unroll
                for (int m = 0; m < 2; ++m)
                    ldsm4(af[m], aB + aRowOff[m] + koff);
                #pragma unroll
                for (int p = 0; p < 4; ++p)
                    ldsm4(bf_[p], bB + bRowOff[p] + koff);

                #pragma unroll
                for (int m = 0; m < 2; ++m)
                    #pragma unroll
                    for (int p = 0; p < 4; ++p) {
                        mma16832s8(acc[m][2 * p],     af[m], &bf_[p][0]);
                        mma16832s8(acc[m][2 * p + 1], af[m], &bf_[p][2]);
                    }
            }
            __syncthreads();
            if (t == 0) {
                if (c < 2) {
                    const char* gA1 = g_i8 + (size_t)ti * TILE_B;
                    const char* gB1 = g_i8 + (size_t)tj * TILE_B;
                    const uint32_t mb = sbase + SM_MBAR + (uint32_t)buf * 8;
                    MB_EXPECT_TX(mb, 2 * CHUNK_B);
                    bulk_g2s(sbase + SM_A(buf), gA1 + (size_t)(c + 2) * CHUNK_B, CHUNK_B, mb);
                    bulk_g2s(sbase + SM_B(buf), gB1 + (size_t)(c + 2) * CHUNK_B, CHUNK_B, mb);
                } else if (has_next) {
                    const uint32_t mb = sbase + SM_MBAR + (uint32_t)buf * 8;
                    MB_EXPECT_TX(mb, 2 * CHUNK_B);
                    bulk_g2s(sbase + SM_A(buf), gA2 + (size_t)(c - 2) * CHUNK_B, CHUNK_B, mb);
                    bulk_g2s(sbase + SM_B(buf), gB2 + (size_t)(c - 2) * CHUNK_B, CHUNK_B, mb);
                }
            }
        }

        // -------- fused epilogue (packed f32x2): dequant -> L2 -> kernels ----
        // C[row][col]: row = wrow + m*16 + (lane>>2) + 8*h
        //              col = wcol + n*8 + (lane&3)*2 + {0,1}
        const int   rA = wrow + (lane >> 2);
        const int   cB = wcol + (lane & 3) * 2;
        const float* sqaRow = g_sq    + ti * 128 + rA;
        const float* scaRow = g_scale + ti * 128 + rA;
        const float* sqbRow = g_sq    + tj * 128 + cB;
        const float* scbRow = g_scale + tj * 128 + cB;

        u64t saDup[4], siDup[4];
        #pragma unroll
        for (int m = 0; m < 2; ++m)
            #pragma unroll
            for (int h = 0; h < 2; ++h) {
                float va = sqaRow[m * 16 + h * 8];
                float vs = scaRow[m * 16 + h * 8];
                saDup[m * 2 + h] = f2pack(va, va);
                siDup[m * 2 + h] = f2pack(vs, vs);
            }
        u64t sbp[8], m2sj[8];
        #pragma unroll
        for (int n = 0; n < 8; ++n) {
            sbp[n]  = *(const u64t*)(sqbRow + n * 8);
            m2sj[n] = f2fma(*(const u64t*)(scbRow + n * 8), M2, ZERO);
        }

        u64t tsp = ZERO;
        #pragma unroll
        for (int m = 0; m < 2; ++m)
            #pragma unroll
            for (int n = 0; n < 8; ++n)
                #pragma unroll
                for (int h = 0; h < 2; ++h) {
                    float f0 = __int2float_rn(acc[m][n][2 * h]);
                    float f1 = __int2float_rn(acc[m][n][2 * h + 1]);
                    u64t dp   = f2pack(f0, f1);
                    u64t tpd  = f2fma(dp, siDup[m * 2 + h], ZERO);  // acc*s_i
                    u64t sumS = f2fma(saDup[m * 2 + h], ONE, sbp[n]);
                    u64t l2p  = f2fma(tpd, m2sj[n], sumS);          // L2
                    u64t xp   = f2fma(l2p, NCD, ZERO);
                    float x0, x1;
                    f2unpack(xp, x0, x1);
                    u64t up  = f2pack(fast_ex2(x0), fast_ex2(x1));
                    u64t a_  = f2fma(up, up, up);        // u^2 + u
                    u64t u2  = f2fma(up, up, ZERO);
                    u64t u4  = f2fma(u2, u2, ZERO);
                    u64t b_  = f2fma(u4, u4, u4);        // u^8 + u^4
                    u64t u8  = f2fma(u4, u4, ZERO);
                    tsp = f2fma(u8, u8, tsp);            // + u^16
                    tsp = f2fma(a_, ONE, tsp);
                    tsp = f2fma(b_, ONE, tsp);
                }
        float tlo, thi;
        f2unpack(tsp, tlo, thi);
        float tsum = tlo + thi;

        #pragma unroll
        for (int o = 16; o; o >>= 1) tsum += __shfl_xor_sync(0xffffffffu, tsum, o);
        float* red = (float*)(smem + SM_RED);
        if (lane == 0) red[wid] = tsum;
        __syncthreads();
        if (wid == 0) {
            float v = (lane < 8) ? red[lane] : 0.f;
            #pragma unroll
            for (int o = 4; o; o >>= 1) v += __shfl_xor_sync(0xffffffffu, v, o);
            if (lane == 0) {
                bool  si   = (ti * 128) < B;
                bool  sj   = (tj * 128) < B;
                float w    = (ti == tj) ? 1.f : 2.f;
                float sgnw = (si == sj) ? w : -w;
                atomicAdd(&g_accum, (double)(v * sgnw));
            }
        }

        if (!has_next) break;
        idx = nidx; ti = ti2; tj = tj2;
    }
}

// ---------------------------------------------------------------------------
__global__ void k_final(float* out, int B) {
    out[0] = (float)(g_accum / ((double)B * (double)B));
}

// ---------------------------------------------------------------------------
extern "C" void kernel_launch(void* const* d_in, const int* in_sizes, int n_in,
                              void* d_out, int out_size) {
    const float* src = (const float*)d_in[0];
    const float* tgt = (const float*)d_in[1];
    const int B = in_sizes[0] / DDIM;   // 4096
    const int N = 2 * B;                // 8192
    const int NT = N / 128;             // 64

    cudaFuncSetAttribute(k_mmd, cudaFuncAttributeMaxDynamicSharedMemorySize, SM_TOTAL);

    k_prep<<<N / 64, 256>>>(src, tgt, B);
    k_bw<<<1, 256>>>(B);
    const int ntri = NT * (NT + 1) / 2; // 2080
    const int ncta = (ntri < NCTA) ? ntri : NCTA;
    k_mmd<<<ncta, 256, SM_TOTAL>>>(B, NT, ntri);
    k_final<<<1, 1>>>((float*)d_out, B);
}